// round 1
// baseline (speedup 1.0000x reference)
#include <cuda_runtime.h>

#define N_NODES 10000
#define N_EDGES 320000
#define F 128
#define F4 32     // F/4
#define CLS 64
#define CLS4 16

// ---------------- device scratch (no allocations allowed) ----------------
__device__ int   g_rowptr[N_NODES + 1];
__device__ int   g_cnt[N_NODES];
__device__ int   g_cur[N_NODES];
__device__ int   g_eids[N_EDGES];
__device__ float g_A[N_NODES * F];
__device__ float g_B[N_NODES * F];
__device__ float g_C[N_NODES * F];

// ---------------- CSR build ----------------
__global__ void k_zero_cnt() {
    int i = blockIdx.x * blockDim.x + threadIdx.x;
    if (i < N_NODES) g_cnt[i] = 0;
}

__global__ void k_hist(const int* __restrict__ dst) {
    int e = blockIdx.x * blockDim.x + threadIdx.x;
    if (e < N_EDGES) atomicAdd(&g_cnt[dst[e]], 1);
}

// single-block exclusive scan over 10000 counts; also seeds the scatter cursor
__global__ void k_scan() {
    __shared__ int sh[1024];
    const int t = threadIdx.x;
    const int ITEMS = 10;                 // 1024*10 >= 10000
    int base = t * ITEMS;
    int loc[ITEMS];
    int run = 0;
    #pragma unroll
    for (int j = 0; j < ITEMS; j++) {
        int i = base + j;
        int c = (i < N_NODES) ? g_cnt[i] : 0;
        loc[j] = run;
        run += c;
    }
    sh[t] = run;
    __syncthreads();
    for (int off = 1; off < 1024; off <<= 1) {
        int v = (t >= off) ? sh[t - off] : 0;
        __syncthreads();
        sh[t] += v;
        __syncthreads();
    }
    int excl = sh[t] - run;
    #pragma unroll
    for (int j = 0; j < ITEMS; j++) {
        int i = base + j;
        if (i < N_NODES) {
            int rp = excl + loc[j];
            g_rowptr[i] = rp;
            g_cur[i]    = rp;
        }
    }
    if (t == 1023) g_rowptr[N_NODES] = sh[1023];
}

__global__ void k_scatter(const int* __restrict__ dst) {
    int e = blockIdx.x * blockDim.x + threadIdx.x;
    if (e < N_EDGES) {
        int p = atomicAdd(&g_cur[dst[e]], 1);
        g_eids[p] = e;
    }
}

// ---------------- layer kernels ----------------
// A[v] = mean over in-edges of edge_feats[e]   (layer 1 only)
__global__ void k_A1(const float* __restrict__ ef) {
    int w    = (blockIdx.x * blockDim.x + threadIdx.x) >> 5;
    int lane = threadIdx.x & 31;
    if (w >= N_NODES) return;
    int r0 = g_rowptr[w], r1 = g_rowptr[w + 1];
    const float4* E4 = (const float4*)ef;
    float4 acc = make_float4(0.f, 0.f, 0.f, 0.f);
    int p = r0;
    int eNxt = (p < r1) ? g_eids[p] : 0;
    while (p < r1) {
        int e = eNxt;
        ++p;
        if (p < r1) eNxt = g_eids[p];
        float4 x = E4[e * F4 + lane];
        acc.x += x.x; acc.y += x.y; acc.z += x.z; acc.w += x.w;
    }
    float inv = 1.f / (float)(r1 - r0);
    acc.x *= inv; acc.y *= inv; acc.z *= inv; acc.w *= inv;
    ((float4*)g_A)[w * F4 + lane] = acc;
}

// A[v] = mean over in-edges of relu(0.5*(C[src]+C[v]) + b)   (layers 2..5)
__global__ void k_Af(const int* __restrict__ src, const float* __restrict__ bias) {
    int w    = (blockIdx.x * blockDim.x + threadIdx.x) >> 5;
    int lane = threadIdx.x & 31;
    if (w >= N_NODES) return;
    int r0 = g_rowptr[w], r1 = g_rowptr[w + 1];
    const float4* C4 = (const float4*)g_C;
    float4 cd = C4[w * F4 + lane];
    float4 bb = ((const float4*)bias)[lane];
    float4 acc = make_float4(0.f, 0.f, 0.f, 0.f);
    int p = r0;
    int sNxt = (p < r1) ? src[g_eids[p]] : 0;
    while (p < r1) {
        int s = sNxt;
        ++p;
        if (p < r1) sNxt = src[g_eids[p]];
        float4 x = C4[s * F4 + lane];
        float tx = fmaxf((x.x + cd.x) * 0.5f + bb.x, 0.f);
        float ty = fmaxf((x.y + cd.y) * 0.5f + bb.y, 0.f);
        float tz = fmaxf((x.z + cd.z) * 0.5f + bb.z, 0.f);
        float tw = fmaxf((x.w + cd.w) * 0.5f + bb.w, 0.f);
        acc.x += tx; acc.y += ty; acc.z += tz; acc.w += tw;
    }
    float inv = 1.f / (float)(r1 - r0);
    acc.x *= inv; acc.y *= inv; acc.z *= inv; acc.w *= inv;
    ((float4*)g_A)[w * F4 + lane] = acc;
}

// B[v] = sum over in-edges of A[src[e]]
__global__ void k_B(const int* __restrict__ src) {
    int w    = (blockIdx.x * blockDim.x + threadIdx.x) >> 5;
    int lane = threadIdx.x & 31;
    if (w >= N_NODES) return;
    int r0 = g_rowptr[w], r1 = g_rowptr[w + 1];
    const float4* A4 = (const float4*)g_A;
    float4 acc = make_float4(0.f, 0.f, 0.f, 0.f);
    int p = r0;
    int sNxt = (p < r1) ? src[g_eids[p]] : 0;
    while (p < r1) {
        int s = sNxt;
        ++p;
        if (p < r1) sNxt = src[g_eids[p]];
        float4 x = A4[s * F4 + lane];
        acc.x += x.x; acc.y += x.y; acc.z += x.z; acc.w += x.w;
    }
    ((float4*)g_B)[w * F4 + lane] = acc;
}

// C = B @ W^T, K = 128 fixed, output row stride = BN (no bias; bias applied per-edge)
template <int BN, int TN>
__global__ void k_gemm(const float* __restrict__ W) {
    constexpr int BM = 64, BK = 16, TM = 4;
    constexpr int NX = BN / TN;            // 16
    __shared__ float As[BK][BM + 4];
    __shared__ float Ws[BK][BN + 4];
    const int tid = threadIdx.x;
    const int tx  = tid % NX;
    const int ty  = tid / NX;
    const int m0  = blockIdx.x * BM;

    float acc[TM][TN];
    #pragma unroll
    for (int i = 0; i < TM; i++)
        #pragma unroll
        for (int j = 0; j < TN; j++) acc[i][j] = 0.f;

    for (int kc = 0; kc < F; kc += BK) {
        // load B tile (BM x BK), transposed into As[k][m]
        {
            int m  = tid >> 2;
            int k4 = (tid & 3) * 4;
            int gm = m0 + m;
            float4 v = make_float4(0.f, 0.f, 0.f, 0.f);
            if (gm < N_NODES) v = *(const float4*)(g_B + gm * F + kc + k4);
            As[k4 + 0][m] = v.x; As[k4 + 1][m] = v.y;
            As[k4 + 2][m] = v.z; As[k4 + 3][m] = v.w;
        }
        // load W tile (BN x BK), transposed into Ws[k][n]
        #pragma unroll
        for (int r = 0; r < (BN * BK) / (256 * 4); r++) {
            int idx = tid + r * 256;
            int n   = idx >> 2;
            int kw  = (idx & 3) * 4;
            float4 v = *(const float4*)(W + n * F + kc + kw);
            Ws[kw + 0][n] = v.x; Ws[kw + 1][n] = v.y;
            Ws[kw + 2][n] = v.z; Ws[kw + 3][n] = v.w;
        }
        __syncthreads();
        #pragma unroll
        for (int kk = 0; kk < BK; kk++) {
            float4 a = *(const float4*)&As[kk][ty * TM];
            float av[TM] = {a.x, a.y, a.z, a.w};
            float wreg[TN];
            #pragma unroll
            for (int j = 0; j < TN; j += 4)
                *(float4*)&wreg[j] = *(const float4*)&Ws[kk][tx * TN + j];
            #pragma unroll
            for (int i = 0; i < TM; i++)
                #pragma unroll
                for (int j = 0; j < TN; j++)
                    acc[i][j] += av[i] * wreg[j];
        }
        __syncthreads();
    }
    #pragma unroll
    for (int i = 0; i < TM; i++) {
        int gm = m0 + ty * TM + i;
        if (gm < N_NODES) {
            #pragma unroll
            for (int j = 0; j < TN; j += 4)
                *(float4*)(g_C + gm * BN + tx * TN + j) = *(float4*)&acc[i][j];
        }
    }
}

// out[e] = 0.5*(C5[src]+C5[dst]) + b5   (no relu; C5 stride = 64)
__global__ void k_out(const int* __restrict__ src, const int* __restrict__ dst,
                      const float* __restrict__ b5, float* __restrict__ out) {
    int i = blockIdx.x * blockDim.x + threadIdx.x;
    if (i >= N_EDGES * CLS4) return;
    int e = i >> 4;
    int c = i & 15;
    int s = src[e], d = dst[e];
    const float4* C4 = (const float4*)g_C;
    float4 xs = C4[s * CLS4 + c];
    float4 xd = C4[d * CLS4 + c];
    float4 bb = ((const float4*)b5)[c];
    float4 o;
    o.x = (xs.x + xd.x) * 0.5f + bb.x;
    o.y = (xs.y + xd.y) * 0.5f + bb.y;
    o.z = (xs.z + xd.z) * 0.5f + bb.z;
    o.w = (xs.w + xd.w) * 0.5f + bb.w;
    ((float4*)out)[i] = o;
}

// ---------------- launch ----------------
extern "C" void kernel_launch(void* const* d_in, const int* in_sizes, int n_in,
                              void* d_out, int out_size) {
    const float* ef  = (const float*)d_in[0];
    const int*   src = (const int*)d_in[1];
    const int*   dst = (const int*)d_in[2];
    const float* W[5] = {(const float*)d_in[3], (const float*)d_in[5],
                         (const float*)d_in[7], (const float*)d_in[9],
                         (const float*)d_in[11]};
    const float* b[5] = {(const float*)d_in[4], (const float*)d_in[6],
                         (const float*)d_in[8], (const float*)d_in[10],
                         (const float*)d_in[12]};
    float* out = (float*)d_out;

    // CSR by dst (rebuilt every launch; deterministic up to fp reduction order)
    k_zero_cnt<<<(N_NODES + 255) / 256, 256>>>();
    k_hist<<<(N_EDGES + 255) / 256, 256>>>(dst);
    k_scan<<<1, 1024>>>();
    k_scatter<<<(N_EDGES + 255) / 256, 256>>>(dst);

    const int NODE_GRID = (N_NODES + 7) / 8;   // 8 warps/block
    const int GEMM_GRID = (N_NODES + 63) / 64;

    // layer 1
    k_A1<<<NODE_GRID, 256>>>(ef);
    k_B<<<NODE_GRID, 256>>>(src);
    k_gemm<128, 8><<<GEMM_GRID, 256>>>(W[0]);
    // layers 2..4
    for (int l = 1; l < 4; l++) {
        k_Af<<<NODE_GRID, 256>>>(src, b[l - 1]);
        k_B<<<NODE_GRID, 256>>>(src);
        k_gemm<128, 8><<<GEMM_GRID, 256>>>(W[l]);
    }
    // layer 5 (output width 64)
    k_Af<<<NODE_GRID, 256>>>(src, b[3]);
    k_B<<<NODE_GRID, 256>>>(src);
    k_gemm<64, 4><<<GEMM_GRID, 256>>>(W[4]);

    k_out<<<(N_EDGES * CLS4 + 255) / 256, 256>>>(src, dst, b[4], out);
}

// round 5
// speedup vs baseline: 1.2933x; 1.2933x over previous
#include <cuda_runtime.h>

#define N_NODES 10000
#define N_EDGES 320000
#define F 128
#define F4 32     // F/4
#define CLS 64
#define CLS4 16

// ---------------- device scratch (no allocations allowed) ----------------
__device__ int   g_rowptr[N_NODES + 1];
__device__ int   g_cnt[N_NODES];
__device__ int   g_cur[N_NODES];
__device__ int   g_eids[N_EDGES];
__device__ int   g_srcs[N_EDGES];   // src[e] pre-resolved per CSR slot
__device__ float g_A[N_NODES * F];
__device__ float g_B[N_NODES * F];
__device__ float g_C[N_NODES * F];

// ---------------- CSR build ----------------
__global__ void k_zero_cnt() {
    int i = blockIdx.x * blockDim.x + threadIdx.x;
    if (i < N_NODES) g_cnt[i] = 0;
}

__global__ void k_hist(const int* __restrict__ dst) {
    int e = blockIdx.x * blockDim.x + threadIdx.x;
    if (e < N_EDGES) atomicAdd(&g_cnt[dst[e]], 1);
}

// single-block exclusive scan over 10000 counts; seeds scatter cursor
__global__ void k_scan() {
    __shared__ int sh[1024];
    const int t = threadIdx.x;
    const int ITEMS = 10;
    int base = t * ITEMS;
    int loc[ITEMS];
    int run = 0;
    #pragma unroll
    for (int j = 0; j < ITEMS; j++) {
        int i = base + j;
        int c = (i < N_NODES) ? g_cnt[i] : 0;
        loc[j] = run;
        run += c;
    }
    sh[t] = run;
    __syncthreads();
    for (int off = 1; off < 1024; off <<= 1) {
        int v = (t >= off) ? sh[t - off] : 0;
        __syncthreads();
        sh[t] += v;
        __syncthreads();
    }
    int excl = sh[t] - run;
    #pragma unroll
    for (int j = 0; j < ITEMS; j++) {
        int i = base + j;
        if (i < N_NODES) {
            int rp = excl + loc[j];
            g_rowptr[i] = rp;
            g_cur[i]    = rp;
        }
    }
    if (t == 1023) g_rowptr[N_NODES] = sh[1023];
}

__global__ void k_scatter(const int* __restrict__ src, const int* __restrict__ dst) {
    int e = blockIdx.x * blockDim.x + threadIdx.x;
    if (e < N_EDGES) {
        int p = atomicAdd(&g_cur[dst[e]], 1);
        g_eids[p] = e;
        g_srcs[p] = src[e];
    }
}

// ---------------- gather kernels (warp per node, shfl-broadcast indices) ----
// NOTE: macro params must NOT be named x/y/z/w (they'd capture member tokens).
#define ADD4(dstv, srcv) { (dstv).x += (srcv).x; (dstv).y += (srcv).y; \
                           (dstv).z += (srcv).z; (dstv).w += (srcv).w; }

// A[v] = mean over in-edges of edge_feats[e]   (layer 1 only)
__global__ void k_A1(const float* __restrict__ ef) {
    int w    = (blockIdx.x * blockDim.x + threadIdx.x) >> 5;
    int lane = threadIdx.x & 31;
    if (w >= N_NODES) return;
    int r0 = g_rowptr[w], r1 = g_rowptr[w + 1];
    const float4* E4 = (const float4*)ef;
    float4 a0 = make_float4(0.f,0.f,0.f,0.f), a1 = a0, a2 = a0, a3 = a0;
    for (int base = r0; base < r1; base += 32) {
        int rem = r1 - base;
        int n = rem < 32 ? rem : 32;
        int idx = (lane < n) ? g_eids[base + lane] : 0;
        int j = 0;
        for (; j + 4 <= n; j += 4) {
            int s0 = __shfl_sync(0xffffffffu, idx, j);
            int s1 = __shfl_sync(0xffffffffu, idx, j + 1);
            int s2 = __shfl_sync(0xffffffffu, idx, j + 2);
            int s3 = __shfl_sync(0xffffffffu, idx, j + 3);
            float4 x0 = E4[s0 * F4 + lane];
            float4 x1 = E4[s1 * F4 + lane];
            float4 x2 = E4[s2 * F4 + lane];
            float4 x3 = E4[s3 * F4 + lane];
            ADD4(a0, x0); ADD4(a1, x1); ADD4(a2, x2); ADD4(a3, x3);
        }
        for (; j < n; j++) {
            int s = __shfl_sync(0xffffffffu, idx, j);
            float4 xv = E4[s * F4 + lane];
            ADD4(a0, xv);
        }
    }
    a0.x += a1.x + a2.x + a3.x; a0.y += a1.y + a2.y + a3.y;
    a0.z += a1.z + a2.z + a3.z; a0.w += a1.w + a2.w + a3.w;
    float inv = 1.f / (float)(r1 - r0);
    a0.x *= inv; a0.y *= inv; a0.z *= inv; a0.w *= inv;
    ((float4*)g_A)[w * F4 + lane] = a0;
}

// A[v] = mean over in-edges of relu(0.5*(C[src]+C[v]) + b)   (layers 2..5)
__global__ void k_Af(const float* __restrict__ bias) {
    int w    = (blockIdx.x * blockDim.x + threadIdx.x) >> 5;
    int lane = threadIdx.x & 31;
    if (w >= N_NODES) return;
    int r0 = g_rowptr[w], r1 = g_rowptr[w + 1];
    const float4* C4 = (const float4*)g_C;
    float4 cd = C4[w * F4 + lane];
    float4 bb = ((const float4*)bias)[lane];
    // fold: relu(0.5*(x+cd)+b) = relu(0.5*x + (0.5*cd+b))
    float4 cb;
    cb.x = cd.x * 0.5f + bb.x; cb.y = cd.y * 0.5f + bb.y;
    cb.z = cd.z * 0.5f + bb.z; cb.w = cd.w * 0.5f + bb.w;
    float4 a0 = make_float4(0.f,0.f,0.f,0.f), a1 = a0, a2 = a0, a3 = a0;
    for (int base = r0; base < r1; base += 32) {
        int rem = r1 - base;
        int n = rem < 32 ? rem : 32;
        int idx = (lane < n) ? g_srcs[base + lane] : 0;
        int j = 0;
        for (; j + 4 <= n; j += 4) {
            int s0 = __shfl_sync(0xffffffffu, idx, j);
            int s1 = __shfl_sync(0xffffffffu, idx, j + 1);
            int s2 = __shfl_sync(0xffffffffu, idx, j + 2);
            int s3 = __shfl_sync(0xffffffffu, idx, j + 3);
            float4 x0 = C4[s0 * F4 + lane];
            float4 x1 = C4[s1 * F4 + lane];
            float4 x2 = C4[s2 * F4 + lane];
            float4 x3 = C4[s3 * F4 + lane];
            a0.x += fmaxf(fmaf(x0.x, 0.5f, cb.x), 0.f);
            a0.y += fmaxf(fmaf(x0.y, 0.5f, cb.y), 0.f);
            a0.z += fmaxf(fmaf(x0.z, 0.5f, cb.z), 0.f);
            a0.w += fmaxf(fmaf(x0.w, 0.5f, cb.w), 0.f);
            a1.x += fmaxf(fmaf(x1.x, 0.5f, cb.x), 0.f);
            a1.y += fmaxf(fmaf(x1.y, 0.5f, cb.y), 0.f);
            a1.z += fmaxf(fmaf(x1.z, 0.5f, cb.z), 0.f);
            a1.w += fmaxf(fmaf(x1.w, 0.5f, cb.w), 0.f);
            a2.x += fmaxf(fmaf(x2.x, 0.5f, cb.x), 0.f);
            a2.y += fmaxf(fmaf(x2.y, 0.5f, cb.y), 0.f);
            a2.z += fmaxf(fmaf(x2.z, 0.5f, cb.z), 0.f);
            a2.w += fmaxf(fmaf(x2.w, 0.5f, cb.w), 0.f);
            a3.x += fmaxf(fmaf(x3.x, 0.5f, cb.x), 0.f);
            a3.y += fmaxf(fmaf(x3.y, 0.5f, cb.y), 0.f);
            a3.z += fmaxf(fmaf(x3.z, 0.5f, cb.z), 0.f);
            a3.w += fmaxf(fmaf(x3.w, 0.5f, cb.w), 0.f);
        }
        for (; j < n; j++) {
            int s = __shfl_sync(0xffffffffu, idx, j);
            float4 xv = C4[s * F4 + lane];
            a0.x += fmaxf(fmaf(xv.x, 0.5f, cb.x), 0.f);
            a0.y += fmaxf(fmaf(xv.y, 0.5f, cb.y), 0.f);
            a0.z += fmaxf(fmaf(xv.z, 0.5f, cb.z), 0.f);
            a0.w += fmaxf(fmaf(xv.w, 0.5f, cb.w), 0.f);
        }
    }
    a0.x += a1.x + a2.x + a3.x; a0.y += a1.y + a2.y + a3.y;
    a0.z += a1.z + a2.z + a3.z; a0.w += a1.w + a2.w + a3.w;
    float inv = 1.f / (float)(r1 - r0);
    a0.x *= inv; a0.y *= inv; a0.z *= inv; a0.w *= inv;
    ((float4*)g_A)[w * F4 + lane] = a0;
}

// B[v] = sum over in-edges of A[src[e]]
__global__ void k_B() {
    int w    = (blockIdx.x * blockDim.x + threadIdx.x) >> 5;
    int lane = threadIdx.x & 31;
    if (w >= N_NODES) return;
    int r0 = g_rowptr[w], r1 = g_rowptr[w + 1];
    const float4* A4 = (const float4*)g_A;
    float4 a0 = make_float4(0.f,0.f,0.f,0.f), a1 = a0, a2 = a0, a3 = a0;
    for (int base = r0; base < r1; base += 32) {
        int rem = r1 - base;
        int n = rem < 32 ? rem : 32;
        int idx = (lane < n) ? g_srcs[base + lane] : 0;
        int j = 0;
        for (; j + 4 <= n; j += 4) {
            int s0 = __shfl_sync(0xffffffffu, idx, j);
            int s1 = __shfl_sync(0xffffffffu, idx, j + 1);
            int s2 = __shfl_sync(0xffffffffu, idx, j + 2);
            int s3 = __shfl_sync(0xffffffffu, idx, j + 3);
            float4 x0 = A4[s0 * F4 + lane];
            float4 x1 = A4[s1 * F4 + lane];
            float4 x2 = A4[s2 * F4 + lane];
            float4 x3 = A4[s3 * F4 + lane];
            ADD4(a0, x0); ADD4(a1, x1); ADD4(a2, x2); ADD4(a3, x3);
        }
        for (; j < n; j++) {
            int s = __shfl_sync(0xffffffffu, idx, j);
            float4 xv = A4[s * F4 + lane];
            ADD4(a0, xv);
        }
    }
    a0.x += a1.x + a2.x + a3.x; a0.y += a1.y + a2.y + a3.y;
    a0.z += a1.z + a2.z + a3.z; a0.w += a1.w + a2.w + a3.w;
    ((float4*)g_B)[w * F4 + lane] = a0;
}

// ---------------- GEMM: C = B @ W^T (plain fp32 FMA) -----------------------
// BM=64, BN=64, BK=16, 256 threads, TM=4, TN=4. grid=(ceil(M/64), NT/64).
template <int NT>
__global__ __launch_bounds__(256) void k_gemm(const float* __restrict__ W) {
    constexpr int BM = 64, BN = 64, BK = 16;
    __shared__ float As[BK][BM + 4];
    __shared__ float Ws[BK][BN + 4];
    const int tid = threadIdx.x;
    const int tx  = tid & 15;        // 16 col groups of TN=4
    const int ty  = tid >> 4;        // 16 row groups of TM=4
    const int m0  = blockIdx.x * BM;
    const int n0  = blockIdx.y * BN;

    float acc[4][4];
    #pragma unroll
    for (int i = 0; i < 4; i++)
        #pragma unroll
        for (int j = 0; j < 4; j++) acc[i][j] = 0.f;

    for (int kc = 0; kc < F; kc += BK) {
        {   // B tile (BM x BK) -> As[k][m]
            int m  = tid >> 2;
            int k4 = (tid & 3) * 4;
            int gm = m0 + m;
            float4 v = make_float4(0.f, 0.f, 0.f, 0.f);
            if (gm < N_NODES) v = *(const float4*)(g_B + gm * F + kc + k4);
            As[k4 + 0][m] = v.x; As[k4 + 1][m] = v.y;
            As[k4 + 2][m] = v.z; As[k4 + 3][m] = v.w;
        }
        {   // W tile (BN x BK) -> Ws[k][n]
            int n  = tid >> 2;
            int k4 = (tid & 3) * 4;
            float4 v = *(const float4*)(W + (n0 + n) * F + kc + k4);
            Ws[k4 + 0][n] = v.x; Ws[k4 + 1][n] = v.y;
            Ws[k4 + 2][n] = v.z; Ws[k4 + 3][n] = v.w;
        }
        __syncthreads();
        #pragma unroll
        for (int kk = 0; kk < BK; kk++) {
            float4 a = *(const float4*)&As[kk][ty * 4];
            float4 wv = *(const float4*)&Ws[kk][tx * 4];
            float av[4] = {a.x, a.y, a.z, a.w};
            float wr[4] = {wv.x, wv.y, wv.z, wv.w};
            #pragma unroll
            for (int i = 0; i < 4; i++)
                #pragma unroll
                for (int j = 0; j < 4; j++)
                    acc[i][j] = fmaf(av[i], wr[j], acc[i][j]);
        }
        __syncthreads();
    }
    #pragma unroll
    for (int i = 0; i < 4; i++) {
        int gm = m0 + ty * 4 + i;
        if (gm < N_NODES) {
            float4 o = make_float4(acc[i][0], acc[i][1], acc[i][2], acc[i][3]);
            *(float4*)(g_C + gm * NT + n0 + tx * 4) = o;
        }
    }
}

// out[e] = 0.5*(C5[src]+C5[dst]) + b5   (no relu; C5 stride = 64)
__global__ void k_out(const int* __restrict__ src, const int* __restrict__ dst,
                      const float* __restrict__ b5, float* __restrict__ out) {
    int i = blockIdx.x * blockDim.x + threadIdx.x;
    if (i >= N_EDGES * CLS4) return;
    int e = i >> 4;
    int c = i & 15;
    int s = src[e], d = dst[e];
    const float4* C4 = (const float4*)g_C;
    float4 xs = C4[s * CLS4 + c];
    float4 xd = C4[d * CLS4 + c];
    float4 bb = ((const float4*)b5)[c];
    float4 o;
    o.x = (xs.x + xd.x) * 0.5f + bb.x;
    o.y = (xs.y + xd.y) * 0.5f + bb.y;
    o.z = (xs.z + xd.z) * 0.5f + bb.z;
    o.w = (xs.w + xd.w) * 0.5f + bb.w;
    ((float4*)out)[i] = o;
}

// ---------------- launch ----------------
extern "C" void kernel_launch(void* const* d_in, const int* in_sizes, int n_in,
                              void* d_out, int out_size) {
    const float* ef  = (const float*)d_in[0];
    const int*   src = (const int*)d_in[1];
    const int*   dst = (const int*)d_in[2];
    const float* W[5] = {(const float*)d_in[3], (const float*)d_in[5],
                         (const float*)d_in[7], (const float*)d_in[9],
                         (const float*)d_in[11]};
    const float* b[5] = {(const float*)d_in[4], (const float*)d_in[6],
                         (const float*)d_in[8], (const float*)d_in[10],
                         (const float*)d_in[12]};
    float* out = (float*)d_out;

    k_zero_cnt<<<(N_NODES + 255) / 256, 256>>>();
    k_hist<<<(N_EDGES + 255) / 256, 256>>>(dst);
    k_scan<<<1, 1024>>>();
    k_scatter<<<(N_EDGES + 255) / 256, 256>>>(src, dst);

    const int NODE_GRID = (N_NODES + 7) / 8;   // 8 warps/block
    const dim3 GEMM_GRID_128((N_NODES + 63) / 64, 2);
    const dim3 GEMM_GRID_64((N_NODES + 63) / 64, 1);

    // layer 1
    k_A1<<<NODE_GRID, 256>>>(ef);
    k_B<<<NODE_GRID, 256>>>();
    k_gemm<128><<<GEMM_GRID_128, 256>>>(W[0]);
    // layers 2..4
    for (int l = 1; l < 4; l++) {
        k_Af<<<NODE_GRID, 256>>>(b[l - 1]);
        k_B<<<NODE_GRID, 256>>>();
        k_gemm<128><<<GEMM_GRID_128, 256>>>(W[l]);
    }
    // layer 5 (output width 64)
    k_Af<<<NODE_GRID, 256>>>(b[3]);
    k_B<<<NODE_GRID, 256>>>();
    k_gemm<64><<<GEMM_GRID_64, 256>>>(W[4]);

    k_out<<<(N_EDGES * CLS4 + 255) / 256, 256>>>(src, dst, b[4], out);
}